// round 7
// baseline (speedup 1.0000x reference)
#include <cuda_runtime.h>

#define BB 512      // batch rows = threads per block
#define NW 16       // warps per block
#define LL 100      // labels
#define DLEN 100000
#define GAMMA 0.9f

__device__ float g_per_label[LL];
__device__ unsigned int g_cnt = 0;

__global__ __launch_bounds__(BB, 1) void map_loss_fused_kernel(
    const float* __restrict__ y_pred,   // (B, L)
    const float* __restrict__ y_true,   // (B, L)
    const int*   __restrict__ index,    // (B,)
    const float* __restrict__ u_all,    // (L, DLEN)
    const float* __restrict__ u_pos,    // (L, DLEN)
    float* __restrict__ out)
{
    __shared__ float s_fp[BB];
    __shared__ float s_fpp[BB + 8];     // compacted positive fp (+pad)
    __shared__ int   s_prow[BB];        // original row of each positive slot
    __shared__ float s_ua[BB];          // u_all value, indexed by ROW
    __shared__ float s_up[BB];          // u_pos value, indexed by ROW
    __shared__ int   s_wcnt[NW];
    __shared__ float s_wsum[NW];
    __shared__ int   s_last;

    const int l    = blockIdx.x;
    const int t    = threadIdx.x;
    const int warp = t >> 5;
    const int lane = t & 31;

    // ---- issue ALL independent global loads immediately ----
    const int   idx  = index[t];                 // no dependencies
    const float fp_i = y_pred[t * LL + l];       // no dependencies
    const float yt   = y_true[t * LL + l];       // no dependencies
    // u gathers depend only on idx (chain depth 2). Unconditional; kept in
    // REGISTERS so the ~1200cyc latency overlaps the mainloop below.
    const float ua_v = u_all[(long long)l * DLEN + idx];
    const float up_v = u_pos[(long long)l * DLEN + idx];

    const bool pos_i = (yt == 1.0f);
    s_fp[t]  = fp_i;
    s_fpp[t] = -1e30f;                  // pad/clamped reads -> relu = 0
    if (t < 8) s_fpp[BB + t] = -1e30f;

    const unsigned m = __ballot_sync(0xffffffffu, pos_i);
    if (lane == 0) s_wcnt[warp] = __popc(m);
    __syncthreads();

    // ---- prefix over warp counts; deterministic compaction ----
    int base = 0, total = 0;
#pragma unroll
    for (int w = 0; w < NW; w++) {
        int cc = s_wcnt[w];
        if (w < warp) base += cc;
        total += cc;
    }
    if (pos_i) {
        const int off = base + __popc(m & ((1u << lane) - 1u));
        s_fpp[off]  = fp_i;
        s_prow[off] = t;
    }
    const int n_pos = total;                      // >= 1
    const int np4   = ((n_pos + 7) & ~7) >> 2;    // padded float4 count (even)
    __syncthreads();

    // ---- work assignment (block-uniform) ----
    const bool split2    = (2 * n_pos <= BB);
    const int  n_act_thr = split2 ? (2 * n_pos) : n_pos;
    const int  n_act_wrp = (n_act_thr + 31) >> 5;

    bool act = false;
    int  p = 0, half = 0;
    float S_all = 0.0f, S_pos = 0.0f;

    if (warp < n_act_wrp) {            // WARP-UNIFORM: idle warps skip entirely
        act  = t < n_act_thr;
        p    = split2 ? (t >> 1) : t;
        half = split2 ? (t & 1) : 0;
        const float c = act ? (1.0f - s_fpp[p]) : -1e30f;

        const float4* fp4 = reinterpret_cast<const float4*>(s_fp);
        float A0 = 0.f, A1 = 0.f, A2 = 0.f, A3 = 0.f;
        if (split2) {
            // interleaved halves: warp touches two adjacent 16B chunks -> no
            // bank conflicts (previous half*64 split was 1024B apart = same banks)
#pragma unroll 8
            for (int jj = 0; jj < 64; jj++) {
                float4 v = fp4[2 * jj + half];
                float d0 = fmaxf(c + v.x, 0.0f);
                float d1 = fmaxf(c + v.y, 0.0f);
                float d2 = fmaxf(c + v.z, 0.0f);
                float d3 = fmaxf(c + v.w, 0.0f);
                A0 = fmaf(d0, d0, A0); A1 = fmaf(d1, d1, A1);
                A2 = fmaf(d2, d2, A2); A3 = fmaf(d3, d3, A3);
            }
        } else {
#pragma unroll 8
            for (int j = 0; j < 128; j++) {
                float4 v = fp4[j];
                float d0 = fmaxf(c + v.x, 0.0f);
                float d1 = fmaxf(c + v.y, 0.0f);
                float d2 = fmaxf(c + v.z, 0.0f);
                float d3 = fmaxf(c + v.w, 0.0f);
                A0 = fmaf(d0, d0, A0); A1 = fmaf(d1, d1, A1);
                A2 = fmaf(d2, d2, A2); A3 = fmaf(d3, d3, A3);
            }
        }
        S_all = (A0 + A1) + (A2 + A3);

        const float4* fpp4 = reinterpret_cast<const float4*>(s_fpp);
        float P0 = 0.f, P1 = 0.f, P2 = 0.f, P3 = 0.f;
        if (split2) {
            const int h = np4 >> 1;
            for (int jj = 0; jj < h; jj++) {
                float4 v = fpp4[2 * jj + half];
                float d0 = fmaxf(c + v.x, 0.0f);
                float d1 = fmaxf(c + v.y, 0.0f);
                float d2 = fmaxf(c + v.z, 0.0f);
                float d3 = fmaxf(c + v.w, 0.0f);
                P0 = fmaf(d0, d0, P0); P1 = fmaf(d1, d1, P1);
                P2 = fmaf(d2, d2, P2); P3 = fmaf(d3, d3, P3);
            }
        } else {
            for (int j = 0; j < np4; j++) {
                float4 v = fpp4[j];
                float d0 = fmaxf(c + v.x, 0.0f);
                float d1 = fmaxf(c + v.y, 0.0f);
                float d2 = fmaxf(c + v.z, 0.0f);
                float d3 = fmaxf(c + v.w, 0.0f);
                P0 = fmaf(d0, d0, P0); P1 = fmaf(d1, d1, P1);
                P2 = fmaf(d2, d2, P2); P3 = fmaf(d3, d3, P3);
            }
        }
        S_pos = (P0 + P1) + (P2 + P3);

        // Combine halves — all 32 lanes execute (warp-uniform; no deadlock).
        if (split2) {
            S_all += __shfl_xor_sync(0xffffffffu, S_all, 1);
            S_pos += __shfl_xor_sync(0xffffffffu, S_pos, 1);
        }
    }

    // ---- stage u values to SMEM now (loads completed during mainloop) ----
    s_ua[t] = ua_v;
    s_up[t] = up_v;
    __syncthreads();

    float contrib = 0.0f;
    if (act && half == 0) {
        const int   row = s_prow[p];
        const float ua  = s_ua[row];
        const float up  = s_up[row];
        const float ua_new = (1.0f - GAMMA) * ua + GAMMA * (S_all * (1.0f / (float)BB));
        const float up_new = (1.0f - GAMMA) * up + GAMMA * (S_pos * (1.0f / (float)BB));
        contrib = (up_new * S_all - ua_new * S_pos) / (ua_new * ua_new);
    }

    // ---- reduction: warp shuffle + one cross-warp fold (deterministic) ----
    float v = contrib;
#pragma unroll
    for (int off = 16; off > 0; off >>= 1)
        v += __shfl_down_sync(0xffffffffu, v, off);
    if (lane == 0) s_wsum[warp] = v;
    __syncthreads();

    if (warp == 0) {
        float v2 = (lane < NW) ? s_wsum[lane] : 0.0f;
#pragma unroll
        for (int off = 16; off > 0; off >>= 1)
            v2 += __shfl_down_sync(0xffffffffu, v2, off);
        if (lane == 0) {
            g_per_label[l] = v2 / ((float)n_pos * (float)BB);
            __threadfence();
            const unsigned old = atomicAdd(&g_cnt, 1u);
            s_last = (old == LL - 1) ? 1 : 0;
        }
    }
    __syncthreads();

    // ---- last block folds the 100 per-label values (fixed order) ----
    if (s_last && warp == 0) {
        __threadfence();
        volatile float* gp = g_per_label;
        float a = 0.0f;
#pragma unroll
        for (int j = 0; j < 4; j++) {
            const int idx2 = lane + j * 32;
            if (idx2 < LL) a += gp[idx2];
        }
#pragma unroll
        for (int off = 16; off > 0; off >>= 1)
            a += __shfl_down_sync(0xffffffffu, a, off);
        if (lane == 0) {
            out[0] = a / (float)LL;
            g_cnt = 0;                 // reset for next graph replay
        }
    }
}

extern "C" void kernel_launch(void* const* d_in, const int* in_sizes, int n_in,
                              void* d_out, int out_size) {
    const float* y_pred = (const float*)d_in[0];
    const float* y_true = (const float*)d_in[1];
    const int*   index  = (const int*)d_in[2];
    const float* u_all  = (const float*)d_in[3];
    const float* u_pos  = (const float*)d_in[4];
    float* out = (float*)d_out;

    map_loss_fused_kernel<<<LL, BB>>>(y_pred, y_true, index, u_all, u_pos, out);
}

// round 8
// speedup vs baseline: 1.0238x; 1.0238x over previous
#include <cuda_runtime.h>

#define BB 512      // batch rows = threads per block
#define NW 16       // warps per block
#define LL 100      // labels
#define NB (2 * LL) // 2 blocks per label
#define DLEN 100000
#define GAMMA 0.9f

__device__ float g_part[NB];
__device__ unsigned int g_cnt = 0;

// Mainloop over this thread's 1/K interleaved slice. K is compile-time.
template<int K>
__device__ __forceinline__ void compute_sums(
    const float4* __restrict__ fp4, const float4* __restrict__ fpp4,
    int np4, float c, int sub, float& S_all, float& S_pos)
{
    float A0 = 0.f, A1 = 0.f, A2 = 0.f, A3 = 0.f;
#pragma unroll 8
    for (int jj = 0; jj < 128 / K; jj++) {
        float4 v = fp4[K * jj + sub];
        float d0 = fmaxf(c + v.x, 0.0f);
        float d1 = fmaxf(c + v.y, 0.0f);
        float d2 = fmaxf(c + v.z, 0.0f);
        float d3 = fmaxf(c + v.w, 0.0f);
        A0 = fmaf(d0, d0, A0); A1 = fmaf(d1, d1, A1);
        A2 = fmaf(d2, d2, A2); A3 = fmaf(d3, d3, A3);
    }
    S_all = (A0 + A1) + (A2 + A3);

    float P0 = 0.f, P1 = 0.f, P2 = 0.f, P3 = 0.f;
    const int h = np4 / K;              // np4 is a multiple of 4
#pragma unroll 4
    for (int jj = 0; jj < h; jj++) {
        float4 v = fpp4[K * jj + sub];
        float d0 = fmaxf(c + v.x, 0.0f);
        float d1 = fmaxf(c + v.y, 0.0f);
        float d2 = fmaxf(c + v.z, 0.0f);
        float d3 = fmaxf(c + v.w, 0.0f);
        P0 = fmaf(d0, d0, P0); P1 = fmaf(d1, d1, P1);
        P2 = fmaf(d2, d2, P2); P3 = fmaf(d3, d3, P3);
    }
    S_pos = (P0 + P1) + (P2 + P3);
}

// 2 blocks per label: block (l, h) handles half of the positive slots.
__global__ __launch_bounds__(BB, 2) void map_loss_fused_kernel(
    const float* __restrict__ y_pred,   // (B, L)
    const float* __restrict__ y_true,   // (B, L)
    const int*   __restrict__ index,    // (B,)
    const float* __restrict__ u_all,    // (L, DLEN)
    const float* __restrict__ u_pos,    // (L, DLEN)
    float* __restrict__ out)
{
    __shared__ float s_fp[BB];
    __shared__ float s_fpp[BB + 16];    // compacted positive fp (+pad to x16)
    __shared__ int   s_prow[BB];        // original row of each positive slot
    __shared__ float s_ua[BB];          // u_all by ROW
    __shared__ float s_up[BB];          // u_pos by ROW
    __shared__ int   s_wcnt[NW];
    __shared__ float s_wsum[NW];
    __shared__ int   s_last;

    const int l    = blockIdx.x >> 1;
    const int hb   = blockIdx.x & 1;    // which half of positive slots
    const int t    = threadIdx.x;
    const int warp = t >> 5;
    const int lane = t & 31;

    // ---- issue all independent global loads immediately ----
    const int   idx  = index[t];
    const float fp_i = y_pred[t * LL + l];
    const float yt   = y_true[t * LL + l];
    const float ua_v = u_all[(long long)l * DLEN + idx];   // in regs through mainloop
    const float up_v = u_pos[(long long)l * DLEN + idx];

    const bool pos_i = (yt == 1.0f);
    s_fp[t]  = fp_i;
    s_fpp[t] = -1e30f;                  // pad/clamped reads -> relu = 0
    if (t < 16) s_fpp[BB + t] = -1e30f;

    const unsigned m = __ballot_sync(0xffffffffu, pos_i);
    if (lane == 0) s_wcnt[warp] = __popc(m);
    __syncthreads();

    // ---- prefix over warp counts; deterministic compaction ----
    int base = 0, total = 0;
#pragma unroll
    for (int w = 0; w < NW; w++) {
        int cc = s_wcnt[w];
        if (w < warp) base += cc;
        total += cc;
    }
    if (pos_i) {
        const int off = base + __popc(m & ((1u << lane) - 1u));
        s_fpp[off]  = fp_i;
        s_prow[off] = t;
    }
    const int n_pos = total;                       // label-global (>=1)
    const int np4   = ((n_pos + 15) & ~15) >> 2;   // float4 count, multiple of 4
    __syncthreads();

    // ---- this block's slot range ----
    const int c0    = (n_pos + 1) >> 1;
    const int sbeg  = hb ? c0 : 0;
    const int cnt   = hb ? (n_pos - c0) : c0;      // rows this block owns

    // ---- K selection (block-uniform, compile-time instantiations) ----
    const int n4 = 4 * cnt, n2 = 2 * cnt;
    int n_act_thr, Ksel;
    if (n4 <= BB)      { Ksel = 4; n_act_thr = n4; }
    else if (n2 <= BB) { Ksel = 2; n_act_thr = n2; }
    else               { Ksel = 1; n_act_thr = cnt; }
    const int n_act_wrp = (n_act_thr + 31) >> 5;

    bool  act = false;
    int   slot = 0, sub = 0;
    float S_all = 0.0f, S_pos = 0.0f;

    if (warp < n_act_wrp) {             // warp-uniform; idle warps skip
        act = t < n_act_thr;
        const float4* fp4  = reinterpret_cast<const float4*>(s_fp);
        const float4* fpp4 = reinterpret_cast<const float4*>(s_fpp);

        if (Ksel == 4) {
            slot = sbeg + (t >> 2); sub = t & 3;
            const float c = act ? (1.0f - s_fpp[slot]) : -1e30f;
            compute_sums<4>(fp4, fpp4, np4, c, sub, S_all, S_pos);
            S_all += __shfl_xor_sync(0xffffffffu, S_all, 1);
            S_all += __shfl_xor_sync(0xffffffffu, S_all, 2);
            S_pos += __shfl_xor_sync(0xffffffffu, S_pos, 1);
            S_pos += __shfl_xor_sync(0xffffffffu, S_pos, 2);
        } else if (Ksel == 2) {
            slot = sbeg + (t >> 1); sub = t & 1;
            const float c = act ? (1.0f - s_fpp[slot]) : -1e30f;
            compute_sums<2>(fp4, fpp4, np4, c, sub, S_all, S_pos);
            S_all += __shfl_xor_sync(0xffffffffu, S_all, 1);
            S_pos += __shfl_xor_sync(0xffffffffu, S_pos, 1);
        } else {
            slot = sbeg + t; sub = 0;
            const float c = act ? (1.0f - s_fpp[slot]) : -1e30f;
            compute_sums<1>(fp4, fpp4, np4, c, sub, S_all, S_pos);
        }
    }

    // ---- stage u values (loads completed during mainloop) ----
    s_ua[t] = ua_v;
    s_up[t] = up_v;
    __syncthreads();

    float contrib = 0.0f;
    if (act && sub == 0) {
        const int   row = s_prow[slot];
        const float ua  = s_ua[row];
        const float up  = s_up[row];
        const float ua_new = (1.0f - GAMMA) * ua + GAMMA * (S_all * (1.0f / (float)BB));
        const float up_new = (1.0f - GAMMA) * up + GAMMA * (S_pos * (1.0f / (float)BB));
        contrib = (up_new * S_all - ua_new * S_pos) / (ua_new * ua_new);
    }

    // ---- block reduction: warp shuffle + cross-warp fold ----
    float v = contrib;
#pragma unroll
    for (int off = 16; off > 0; off >>= 1)
        v += __shfl_down_sync(0xffffffffu, v, off);
    if (lane == 0) s_wsum[warp] = v;
    __syncthreads();

    if (warp == 0) {
        float v2 = (lane < NW) ? s_wsum[lane] : 0.0f;
#pragma unroll
        for (int off = 16; off > 0; off >>= 1)
            v2 += __shfl_down_sync(0xffffffffu, v2, off);
        if (lane == 0) {
            g_part[blockIdx.x] = v2 / ((float)n_pos * (float)BB);
            __threadfence();
            const unsigned old = atomicAdd(&g_cnt, 1u);
            s_last = (old == NB - 1) ? 1 : 0;
        }
    }
    __syncthreads();

    // ---- last block folds the 200 partials in fixed order ----
    if (s_last && warp == 0) {
        __threadfence();
        volatile float* gp = g_part;
        float a = 0.0f;
#pragma unroll
        for (int j = 0; j < (NB + 31) / 32; j++) {
            const int i2 = lane + j * 32;
            if (i2 < NB) a += gp[i2];
        }
#pragma unroll
        for (int off = 16; off > 0; off >>= 1)
            a += __shfl_down_sync(0xffffffffu, a, off);
        if (lane == 0) {
            out[0] = a / (float)LL;
            g_cnt = 0;                  // reset for next graph replay
        }
    }
}

extern "C" void kernel_launch(void* const* d_in, const int* in_sizes, int n_in,
                              void* d_out, int out_size) {
    const float* y_pred = (const float*)d_in[0];
    const float* y_true = (const float*)d_in[1];
    const int*   index  = (const int*)d_in[2];
    const float* u_all  = (const float*)d_in[3];
    const float* u_pos  = (const float*)d_in[4];
    float* out = (float*)d_out;

    map_loss_fused_kernel<<<NB, BB>>>(y_pred, y_true, index, u_all, u_pos, out);
}